// round 3
// baseline (speedup 1.0000x reference)
#include <cuda_runtime.h>
#include <cuda_bf16.h>
#include <stdint.h>

#define N_EMB 8192
#define D     512
#define N_POS 4096
#define N_NEG 16384

#define NSPLIT 16
#define N_PER_SPLIT (N_EMB / NSPLIT)   // 512 columns per CTA

#define BM 128
#define BN 128
#define BK 32
#define PAD 8

// Scratch (allocation-free rule: __device__ globals)
static __device__ float         g_e[(size_t)N_EMB * D];     // normalized fp32 (16 MB)
static __device__ __nv_bfloat16 g_eb[(size_t)N_EMB * D];    // normalized bf16 (8 MB)
static __device__ float         g_partial[NSPLIT * N_POS];  // partial exp-sums
static __device__ float         g_acc[3];                   // loss_sum, pos_sum, neg_sum

// ---------------------------------------------------------------------------
// Kernel 0: zero accumulators (graph is replayed; must re-init every launch)
// ---------------------------------------------------------------------------
__global__ void init_kernel() {
    if (threadIdx.x < 3) g_acc[threadIdx.x] = 0.f;
}

// ---------------------------------------------------------------------------
// Kernel 1: row L2-normalize; emit fp32 and bf16 copies.
// One warp per row, 8 rows per 256-thread block.
// ---------------------------------------------------------------------------
__global__ void __launch_bounds__(256) normalize_kernel(const float* __restrict__ emb) {
    int row  = blockIdx.x * 8 + (threadIdx.x >> 5);
    int lane = threadIdx.x & 31;
    const float* src = emb + (size_t)row * D;
    float v[16];
    float ss = 0.f;
#pragma unroll
    for (int i = 0; i < 16; i++) { v[i] = src[lane + 32 * i]; ss += v[i] * v[i]; }
#pragma unroll
    for (int o = 16; o > 0; o >>= 1) ss += __shfl_xor_sync(0xffffffffu, ss, o);
    float rn = rsqrtf(ss);   // norms ~ sqrt(512); max(norm,1e-8) never binds
    float*         dst  = g_e  + (size_t)row * D;
    __nv_bfloat16* dstb = g_eb + (size_t)row * D;
#pragma unroll
    for (int i = 0; i < 16; i++) {
        float e = v[i] * rn;
        dst[lane + 32 * i]  = e;
        dstb[lane + 32 * i] = __float2bfloat16(e);
    }
}

// ---------------------------------------------------------------------------
// Kernel 2: A = e[pos_anchor] (4096 x 512) times B^T = e (8192 x 512),
// fused row-wise sum of exp((sim - 1) / T). Fixed shift M = 1/T is safe
// because cosine sim <= 1. Partial sums per N-split go to g_partial.
// ---------------------------------------------------------------------------
__device__ __forceinline__ void mma16816(float c[4], const uint32_t a[4],
                                         uint32_t b0, uint32_t b1) {
    asm volatile(
        "mma.sync.aligned.m16n8k16.row.col.f32.bf16.bf16.f32 "
        "{%0,%1,%2,%3}, {%4,%5,%6,%7}, {%8,%9}, {%0,%1,%2,%3};\n"
        : "+f"(c[0]), "+f"(c[1]), "+f"(c[2]), "+f"(c[3])
        : "r"(a[0]), "r"(a[1]), "r"(a[2]), "r"(a[3]), "r"(b0), "r"(b1));
}

__global__ void __launch_bounds__(256, 2) gemm_lse_kernel(const int* __restrict__ pos_anchor) {
    __shared__ __nv_bfloat16 As[BM][BK + PAD];
    __shared__ __nv_bfloat16 Bs[BN][BK + PAD];
    __shared__ float rowsum[BM];
    __shared__ int   rowidx[BM];

    const int tid    = threadIdx.x;
    const int wid    = tid >> 5;
    const int lane   = tid & 31;
    const int warp_m = wid >> 2;    // 0..1  (64 rows each)
    const int warp_n = wid & 3;     // 0..3  (32 cols each)
    const int g      = lane >> 2;   // group 0..7
    const int t4     = lane & 3;    // thread-in-group
    const int m_base = blockIdx.x * BM;
    const int n_start = blockIdx.y * N_PER_SPLIT;
    const float inv_t = 1.0f / 0.07f;

    if (tid < BM) {
        rowidx[tid] = pos_anchor[m_base + tid];
        rowsum[tid] = 0.f;
    }

    for (int bn = 0; bn < N_PER_SPLIT; bn += BN) {
        const int n_base = n_start + bn;
        float acc[4][4][4];
#pragma unroll
        for (int a = 0; a < 4; a++)
#pragma unroll
            for (int b = 0; b < 4; b++)
#pragma unroll
                for (int c = 0; c < 4; c++) acc[a][b][c] = 0.f;

        for (int kt = 0; kt < D; kt += BK) {
            __syncthreads();
            // load 128x32 A (gathered rows) + 128x32 B, 8 bf16 per uint4
#pragma unroll
            for (int it = 0; it < 2; it++) {
                int idx = tid + it * 256;     // 0..511
                int r = idx >> 2;             // row 0..127
                int c = (idx & 3) << 3;       // col 0,8,16,24
                *(uint4*)&As[r][c] = *(const uint4*)&g_eb[(size_t)rowidx[r] * D + kt + c];
                *(uint4*)&Bs[r][c] = *(const uint4*)&g_eb[(size_t)(n_base + r) * D + kt + c];
            }
            __syncthreads();
#pragma unroll
            for (int ks = 0; ks < 2; ks++) {
                const int k0 = ks * 16;
                uint32_t a[4][4];
#pragma unroll
                for (int mf = 0; mf < 4; mf++) {
                    int r0 = warp_m * 64 + mf * 16;
                    a[mf][0] = *(const uint32_t*)&As[r0 + g    ][k0 + t4 * 2];
                    a[mf][1] = *(const uint32_t*)&As[r0 + g + 8][k0 + t4 * 2];
                    a[mf][2] = *(const uint32_t*)&As[r0 + g    ][k0 + t4 * 2 + 8];
                    a[mf][3] = *(const uint32_t*)&As[r0 + g + 8][k0 + t4 * 2 + 8];
                }
#pragma unroll
                for (int nf = 0; nf < 4; nf++) {
                    int c0 = warp_n * 32 + nf * 8;
                    uint32_t b0 = *(const uint32_t*)&Bs[c0 + g][k0 + t4 * 2];
                    uint32_t b1 = *(const uint32_t*)&Bs[c0 + g][k0 + t4 * 2 + 8];
#pragma unroll
                    for (int mf = 0; mf < 4; mf++) mma16816(acc[mf][nf], a[mf], b0, b1);
                }
            }
        }

        // epilogue: exp((sim-1)/T) row-sums
#pragma unroll
        for (int mf = 0; mf < 4; mf++) {
            float slo = 0.f, shi = 0.f;
#pragma unroll
            for (int nf = 0; nf < 4; nf++) {
                slo += __expf((acc[mf][nf][0] - 1.f) * inv_t);
                slo += __expf((acc[mf][nf][1] - 1.f) * inv_t);
                shi += __expf((acc[mf][nf][2] - 1.f) * inv_t);
                shi += __expf((acc[mf][nf][3] - 1.f) * inv_t);
            }
            // reduce across the 4 lanes sharing a row
            slo += __shfl_xor_sync(0xffffffffu, slo, 1);
            slo += __shfl_xor_sync(0xffffffffu, slo, 2);
            shi += __shfl_xor_sync(0xffffffffu, shi, 1);
            shi += __shfl_xor_sync(0xffffffffu, shi, 2);
            if (t4 == 0) {
                atomicAdd(&rowsum[warp_m * 64 + mf * 16 + g],     slo);
                atomicAdd(&rowsum[warp_m * 64 + mf * 16 + g + 8], shi);
            }
        }
    }
    __syncthreads();
    if (tid < BM) g_partial[blockIdx.y * N_POS + m_base + tid] = rowsum[tid];
}

// ---------------------------------------------------------------------------
// Kernel 3: one warp per pair. fp32 dot for pos_logit / pos_sim / neg_sim,
// assemble lse from partials, block-reduce, 3 global atomics per block.
// ---------------------------------------------------------------------------
__global__ void __launch_bounds__(256) pairs_kernel(
    const int* __restrict__ pa, const int* __restrict__ pt,
    const int* __restrict__ na, const int* __restrict__ nt) {
    __shared__ float red[3];
    const int tid = threadIdx.x;
    if (tid < 3) red[tid] = 0.f;
    __syncthreads();

    const int w    = blockIdx.x * 8 + (tid >> 5);
    const int lane = tid & 31;
    const float inv_t = 1.0f / 0.07f;

    const bool is_pos = (w < N_POS);
    int ia, ib;
    if (is_pos) { ia = pa[w]; ib = pt[w]; }
    else        { ia = na[w - N_POS]; ib = nt[w - N_POS]; }

    const float* ea = g_e + (size_t)ia * D;
    const float* eb = g_e + (size_t)ib * D;
    float d = 0.f;
#pragma unroll
    for (int k = 0; k < 16; k++) d += ea[lane + 32 * k] * eb[lane + 32 * k];
#pragma unroll
    for (int o = 16; o > 0; o >>= 1) d += __shfl_xor_sync(0xffffffffu, d, o);

    if (is_pos) {
        float s = (lane < NSPLIT) ? g_partial[lane * N_POS + w] : 0.f;
#pragma unroll
        for (int o = 16; o > 0; o >>= 1) s += __shfl_xor_sync(0xffffffffu, s, o);
        if (lane == 0) {
            float lse = inv_t + __logf(s);   // shift-back: M = 1/T
            atomicAdd(&red[0], lse - d * inv_t);
            atomicAdd(&red[1], d);
        }
    } else {
        if (lane == 0) atomicAdd(&red[2], d);
    }
    __syncthreads();
    if (tid < 3) atomicAdd(&g_acc[tid], red[tid]);
}

// ---------------------------------------------------------------------------
// Kernel 4: finalize means into d_out; defensively zero any tail elements.
// ---------------------------------------------------------------------------
__global__ void finalize_kernel(float* out, int out_size) {
    int i = threadIdx.x + blockIdx.x * blockDim.x;
    if (i == 0) {
        out[0] = g_acc[0] / (float)N_POS;
        if (out_size > 1) out[1] = g_acc[1] / (float)N_POS;
        if (out_size > 2) out[2] = g_acc[2] / (float)N_NEG;
    } else if (i < out_size) {
        if (i >= 3) out[i] = 0.f;
    }
}

// ---------------------------------------------------------------------------
extern "C" void kernel_launch(void* const* d_in, const int* in_sizes, int n_in,
                              void* d_out, int out_size) {
    const float* emb = (const float*)d_in[0];
    const int*   pa  = (const int*)d_in[1];
    const int*   pt  = (const int*)d_in[2];
    const int*   na  = (const int*)d_in[3];
    const int*   nt  = (const int*)d_in[4];
    float* out = (float*)d_out;

    init_kernel<<<1, 32>>>();
    normalize_kernel<<<N_EMB / 8, 256>>>(emb);
    gemm_lse_kernel<<<dim3(N_POS / BM, NSPLIT), 256>>>(pa);
    pairs_kernel<<<(N_POS + N_NEG) / 8, 256>>>(pa, pt, na, nt);
    finalize_kernel<<<(out_size + 255) / 256 > 0 ? (out_size + 255) / 256 : 1, 256>>>(out, out_size);
}

// round 4
// speedup vs baseline: 1.0078x; 1.0078x over previous
#include <cuda_runtime.h>
#include <cuda_bf16.h>
#include <stdint.h>

#define N_EMB 8192
#define D     512
#define N_POS 4096
#define N_NEG 16384

#define NSPLIT 16
#define N_PER_SPLIT (N_EMB / NSPLIT)   // 512 columns per CTA

#define BM 128
#define BN 128
#define BK 32
#define PAD 8

// Scratch (allocation-free rule: __device__ globals)
static __device__ float         g_e[(size_t)N_EMB * D];     // normalized fp32 (16 MB)
static __device__ __nv_bfloat16 g_eb[(size_t)N_EMB * D];    // normalized bf16 (8 MB)
static __device__ float         g_partial[NSPLIT * N_POS];  // partial exp-sums
static __device__ float         g_acc[3];                   // loss_sum, pos_sum, neg_sum

// ---------------------------------------------------------------------------
// Kernel 0: zero accumulators (graph is replayed; must re-init every launch)
// ---------------------------------------------------------------------------
__global__ void init_kernel() {
    if (threadIdx.x < 3) g_acc[threadIdx.x] = 0.f;
}

// ---------------------------------------------------------------------------
// Kernel 1: row L2-normalize; emit fp32 and bf16 copies.
// One warp per row, 8 rows per 256-thread block.
// ---------------------------------------------------------------------------
__global__ void __launch_bounds__(256) normalize_kernel(const float* __restrict__ emb) {
    int row  = blockIdx.x * 8 + (threadIdx.x >> 5);
    int lane = threadIdx.x & 31;
    const float* src = emb + (size_t)row * D;
    float v[16];
    float ss = 0.f;
#pragma unroll
    for (int i = 0; i < 16; i++) { v[i] = src[lane + 32 * i]; ss += v[i] * v[i]; }
#pragma unroll
    for (int o = 16; o > 0; o >>= 1) ss += __shfl_xor_sync(0xffffffffu, ss, o);
    float rn = rsqrtf(ss);   // norms ~ sqrt(512); max(norm,1e-8) never binds
    float*         dst  = g_e  + (size_t)row * D;
    __nv_bfloat16* dstb = g_eb + (size_t)row * D;
#pragma unroll
    for (int i = 0; i < 16; i++) {
        float e = v[i] * rn;
        dst[lane + 32 * i]  = e;
        dstb[lane + 32 * i] = __float2bfloat16(e);
    }
}

// ---------------------------------------------------------------------------
// Kernel 2: A = e[pos_anchor] (4096 x 512) times B^T = e (8192 x 512),
// fused row-wise sum of exp((sim - 1) / T). Fixed shift M = 1/T is safe
// because cosine sim <= 1. Partial sums per N-split go to g_partial.
// ---------------------------------------------------------------------------
__device__ __forceinline__ void mma16816(float c[4], const uint32_t a[4],
                                         uint32_t b0, uint32_t b1) {
    asm volatile(
        "mma.sync.aligned.m16n8k16.row.col.f32.bf16.bf16.f32 "
        "{%0,%1,%2,%3}, {%4,%5,%6,%7}, {%8,%9}, {%0,%1,%2,%3};\n"
        : "+f"(c[0]), "+f"(c[1]), "+f"(c[2]), "+f"(c[3])
        : "r"(a[0]), "r"(a[1]), "r"(a[2]), "r"(a[3]), "r"(b0), "r"(b1));
}

__global__ void __launch_bounds__(256, 2) gemm_lse_kernel(const int* __restrict__ pos_anchor) {
    __shared__ __nv_bfloat16 As[BM][BK + PAD];
    __shared__ __nv_bfloat16 Bs[BN][BK + PAD];
    __shared__ float rowsum[BM];
    __shared__ int   rowidx[BM];

    const int tid    = threadIdx.x;
    const int wid    = tid >> 5;
    const int lane   = tid & 31;
    const int warp_m = wid >> 2;    // 0..1  (64 rows each)
    const int warp_n = wid & 3;     // 0..3  (32 cols each)
    const int g      = lane >> 2;   // group 0..7
    const int t4     = lane & 3;    // thread-in-group
    const int m_base = blockIdx.x * BM;
    const int n_start = blockIdx.y * N_PER_SPLIT;
    const float inv_t = 1.0f / 0.07f;

    if (tid < BM) {
        rowidx[tid] = pos_anchor[m_base + tid];
        rowsum[tid] = 0.f;
    }

    for (int bn = 0; bn < N_PER_SPLIT; bn += BN) {
        const int n_base = n_start + bn;
        float acc[4][4][4];
#pragma unroll
        for (int a = 0; a < 4; a++)
#pragma unroll
            for (int b = 0; b < 4; b++)
#pragma unroll
                for (int c = 0; c < 4; c++) acc[a][b][c] = 0.f;

        for (int kt = 0; kt < D; kt += BK) {
            __syncthreads();
            // load 128x32 A (gathered rows) + 128x32 B, 8 bf16 per uint4
#pragma unroll
            for (int it = 0; it < 2; it++) {
                int idx = tid + it * 256;     // 0..511
                int r = idx >> 2;             // row 0..127
                int c = (idx & 3) << 3;       // col 0,8,16,24
                *(uint4*)&As[r][c] = *(const uint4*)&g_eb[(size_t)rowidx[r] * D + kt + c];
                *(uint4*)&Bs[r][c] = *(const uint4*)&g_eb[(size_t)(n_base + r) * D + kt + c];
            }
            __syncthreads();
#pragma unroll
            for (int ks = 0; ks < 2; ks++) {
                const int k0 = ks * 16;
                uint32_t a[4][4];
#pragma unroll
                for (int mf = 0; mf < 4; mf++) {
                    int r0 = warp_m * 64 + mf * 16;
                    a[mf][0] = *(const uint32_t*)&As[r0 + g    ][k0 + t4 * 2];
                    a[mf][1] = *(const uint32_t*)&As[r0 + g + 8][k0 + t4 * 2];
                    a[mf][2] = *(const uint32_t*)&As[r0 + g    ][k0 + t4 * 2 + 8];
                    a[mf][3] = *(const uint32_t*)&As[r0 + g + 8][k0 + t4 * 2 + 8];
                }
#pragma unroll
                for (int nf = 0; nf < 4; nf++) {
                    int c0 = warp_n * 32 + nf * 8;
                    uint32_t b0 = *(const uint32_t*)&Bs[c0 + g][k0 + t4 * 2];
                    uint32_t b1 = *(const uint32_t*)&Bs[c0 + g][k0 + t4 * 2 + 8];
#pragma unroll
                    for (int mf = 0; mf < 4; mf++) mma16816(acc[mf][nf], a[mf], b0, b1);
                }
            }
        }

        // epilogue: exp((sim-1)/T) row-sums
#pragma unroll
        for (int mf = 0; mf < 4; mf++) {
            float slo = 0.f, shi = 0.f;
#pragma unroll
            for (int nf = 0; nf < 4; nf++) {
                slo += __expf((acc[mf][nf][0] - 1.f) * inv_t);
                slo += __expf((acc[mf][nf][1] - 1.f) * inv_t);
                shi += __expf((acc[mf][nf][2] - 1.f) * inv_t);
                shi += __expf((acc[mf][nf][3] - 1.f) * inv_t);
            }
            // reduce across the 4 lanes sharing a row
            slo += __shfl_xor_sync(0xffffffffu, slo, 1);
            slo += __shfl_xor_sync(0xffffffffu, slo, 2);
            shi += __shfl_xor_sync(0xffffffffu, shi, 1);
            shi += __shfl_xor_sync(0xffffffffu, shi, 2);
            if (t4 == 0) {
                atomicAdd(&rowsum[warp_m * 64 + mf * 16 + g],     slo);
                atomicAdd(&rowsum[warp_m * 64 + mf * 16 + g + 8], shi);
            }
        }
    }
    __syncthreads();
    if (tid < BM) g_partial[blockIdx.y * N_POS + m_base + tid] = rowsum[tid];
}

// ---------------------------------------------------------------------------
// Kernel 3: one warp per pair. fp32 dot for pos_logit / pos_sim / neg_sim,
// assemble lse from partials, block-reduce, 3 global atomics per block.
// ---------------------------------------------------------------------------
__global__ void __launch_bounds__(256) pairs_kernel(
    const int* __restrict__ pa, const int* __restrict__ pt,
    const int* __restrict__ na, const int* __restrict__ nt) {
    __shared__ float red[3];
    const int tid = threadIdx.x;
    if (tid < 3) red[tid] = 0.f;
    __syncthreads();

    const int w    = blockIdx.x * 8 + (tid >> 5);
    const int lane = tid & 31;
    const float inv_t = 1.0f / 0.07f;

    const bool is_pos = (w < N_POS);
    int ia, ib;
    if (is_pos) { ia = pa[w]; ib = pt[w]; }
    else        { ia = na[w - N_POS]; ib = nt[w - N_POS]; }

    const float* ea = g_e + (size_t)ia * D;
    const float* eb = g_e + (size_t)ib * D;
    float d = 0.f;
#pragma unroll
    for (int k = 0; k < 16; k++) d += ea[lane + 32 * k] * eb[lane + 32 * k];
#pragma unroll
    for (int o = 16; o > 0; o >>= 1) d += __shfl_xor_sync(0xffffffffu, d, o);

    if (is_pos) {
        float s = (lane < NSPLIT) ? g_partial[lane * N_POS + w] : 0.f;
#pragma unroll
        for (int o = 16; o > 0; o >>= 1) s += __shfl_xor_sync(0xffffffffu, s, o);
        if (lane == 0) {
            float lse = inv_t + __logf(s);   // shift-back: M = 1/T
            atomicAdd(&red[0], lse - d * inv_t);
            atomicAdd(&red[1], d);
        }
    } else {
        if (lane == 0) atomicAdd(&red[2], d);
    }
    __syncthreads();
    if (tid < 3) atomicAdd(&g_acc[tid], red[tid]);
}

// ---------------------------------------------------------------------------
// Kernel 4: finalize means into d_out; defensively zero any tail elements.
// ---------------------------------------------------------------------------
__global__ void finalize_kernel(float* out, int out_size) {
    int i = threadIdx.x + blockIdx.x * blockDim.x;
    if (i == 0) {
        out[0] = g_acc[0] / (float)N_POS;
        if (out_size > 1) out[1] = g_acc[1] / (float)N_POS;
        if (out_size > 2) out[2] = g_acc[2] / (float)N_NEG;
    } else if (i < out_size) {
        if (i >= 3) out[i] = 0.f;
    }
}

// ---------------------------------------------------------------------------
extern "C" void kernel_launch(void* const* d_in, const int* in_sizes, int n_in,
                              void* d_out, int out_size) {
    const float* emb = (const float*)d_in[0];
    const int*   pa  = (const int*)d_in[1];
    const int*   pt  = (const int*)d_in[2];
    const int*   na  = (const int*)d_in[3];
    const int*   nt  = (const int*)d_in[4];
    float* out = (float*)d_out;

    init_kernel<<<1, 32>>>();
    normalize_kernel<<<N_EMB / 8, 256>>>(emb);
    gemm_lse_kernel<<<dim3(N_POS / BM, NSPLIT), 256>>>(pa);
    pairs_kernel<<<(N_POS + N_NEG) / 8, 256>>>(pa, pt, na, nt);
    finalize_kernel<<<(out_size + 255) / 256 > 0 ? (out_size + 255) / 256 : 1, 256>>>(out, out_size);
}